// round 1
// baseline (speedup 1.0000x reference)
#include <cuda_runtime.h>

// Problem constants
#define NN 64
#define CC 64
#define WX 4096
#define FF 64
#define WW 9
#define OW (WX - WW + 1)   // 4088

// Tiling
#define W_TILE 128          // outputs per block in w
#define XT (W_TILE + WW - 1) // 136 floats of x per channel per block
#define THREADS 256
// thread map: tw = tid & 15 (16 w-groups), tf = tid >> 4 (16 f-groups)
// each thread: rf = 4 filters (2 f-pairs), rw = 8 outputs as 2 chunks of 4
//   w_local = tw*4 + p*64, p in {0,1}

// -------- packed f32x2 helpers (Blackwell, PTX-only path) --------
__device__ __forceinline__ unsigned long long ffma2(unsigned long long a,
                                                    unsigned long long b,
                                                    unsigned long long c) {
    unsigned long long d;
    asm("fma.rn.f32x2 %0, %1, %2, %3;" : "=l"(d) : "l"(a), "l"(b), "l"(c));
    return d;
}

__device__ __forceinline__ unsigned long long pack2(float lo, float hi) {
    unsigned long long r;
    asm("mov.b64 %0, {%1, %2};" : "=l"(r) : "f"(lo), "f"(hi));
    return r;
}

__device__ __forceinline__ void unpack2(unsigned long long v, float& lo, float& hi) {
    asm("mov.b64 {%0, %1}, %2;" : "=f"(lo), "=f"(hi) : "l"(v));
}

// -------- pre-packed filter: g_fpk[c][f2][t] = (filt[2*f2,c,t], filt[2*f2+1,c,t]) --------
__device__ float2 g_fpk[CC * (FF / 2) * WW];

__global__ void pack_filt_kernel(const float* __restrict__ filt) {
    int i = blockIdx.x * blockDim.x + threadIdx.x;
    const int total = CC * (FF / 2) * WW;
    if (i >= total) return;
    int t  = i % WW;
    int r  = i / WW;
    int f2 = r % (FF / 2);
    int c  = r / (FF / 2);
    int f  = 2 * f2;
    float a = filt[((size_t)f       * CC + c) * WW + t];
    float b = filt[((size_t)(f + 1) * CC + c) * WW + t];
    g_fpk[i] = make_float2(a, b);
}

// -------- main correlation kernel --------
__global__ __launch_bounds__(THREADS, 2)
void corr1d_kernel(const float* __restrict__ x,
                   const float* __restrict__ bias,
                   float* __restrict__ out) {
    __shared__ float x_s[CC * XT];   // 64 * 136 * 4 = 34816 B

    const int tid = threadIdx.x;
    const int tw  = tid & 15;
    const int tf  = tid >> 4;         // 0..15
    const int fbase = tf * 4;
    const int n   = blockIdx.y;
    const int w0  = blockIdx.x * W_TILE;

    // ---- cooperative x tile load: x[n][c][w0 .. w0+135], zero-fill OOB ----
    {
        const float* xn = x + (size_t)n * CC * WX;
        const int nvec = CC * (XT / 4);           // 64 * 34 float4 loads
        for (int i = tid; i < nvec; i += THREADS) {
            int c = i / (XT / 4);
            int e = i - c * (XT / 4);
            int g = w0 + e * 4;
            float4 v;
            if (g + 3 < WX) {
                v = *reinterpret_cast<const float4*>(xn + (size_t)c * WX + g);
            } else {
                const float* row = xn + (size_t)c * WX;
                v.x = (g + 0 < WX) ? row[g + 0] : 0.0f;
                v.y = (g + 1 < WX) ? row[g + 1] : 0.0f;
                v.z = (g + 2 < WX) ? row[g + 2] : 0.0f;
                v.w = (g + 3 < WX) ? row[g + 3] : 0.0f;
            }
            *reinterpret_cast<float4*>(&x_s[c * XT + e * 4]) = v;
        }
    }
    __syncthreads();

    // ---- accumulators: acc[f2][w], lanes = (f = fbase+2*f2, fbase+2*f2+1) ----
    unsigned long long acc[2][8];
    {
        float b0 = (float)CC * bias[fbase + 0];
        float b1 = (float)CC * bias[fbase + 1];
        float b2 = (float)CC * bias[fbase + 2];
        float b3 = (float)CC * bias[fbase + 3];
        unsigned long long i0 = pack2(b0, b1);
        unsigned long long i1 = pack2(b2, b3);
        #pragma unroll
        for (int w = 0; w < 8; ++w) { acc[0][w] = i0; acc[1][w] = i1; }
    }

    const unsigned long long* fpk_base =
        reinterpret_cast<const unsigned long long*>(g_fpk) + (size_t)(tf * 2) * WW;

    for (int c = 0; c < CC; ++c) {
        // filter pairs for this channel: fp[f2][t]
        unsigned long long fp[2][WW];
        const unsigned long long* fpk = fpk_base + (size_t)c * (FF / 2) * WW;
        #pragma unroll
        for (int f2 = 0; f2 < 2; ++f2)
            #pragma unroll
            for (int t = 0; t < WW; ++t)
                fp[f2][t] = fpk[f2 * WW + t];

        const float* xs = &x_s[c * XT + tw * 4];
        #pragma unroll
        for (int p = 0; p < 2; ++p) {
            const float* xp = xs + p * 64;
            float v[12];
            #pragma unroll
            for (int k = 0; k < 3; ++k) {
                float4 q = *reinterpret_cast<const float4*>(xp + 4 * k);
                v[4 * k + 0] = q.x; v[4 * k + 1] = q.y;
                v[4 * k + 2] = q.z; v[4 * k + 3] = q.w;
            }
            unsigned long long xx[12];
            #pragma unroll
            for (int i = 0; i < 12; ++i) xx[i] = pack2(v[i], v[i]);

            #pragma unroll
            for (int t = 0; t < WW; ++t) {
                #pragma unroll
                for (int w = 0; w < 4; ++w) {
                    acc[0][p * 4 + w] = ffma2(xx[t + w], fp[0][t], acc[0][p * 4 + w]);
                    acc[1][p * 4 + w] = ffma2(xx[t + w], fp[1][t], acc[1][p * 4 + w]);
                }
            }
        }
    }

    // ---- store: per (f2, p): two float4 rows (even f lane, odd f lane) ----
    #pragma unroll
    for (int f2 = 0; f2 < 2; ++f2) {
        #pragma unroll
        for (int p = 0; p < 2; ++p) {
            int wg = w0 + tw * 4 + p * 64;
            if (wg < OW) {
                float lo[4], hi[4];
                #pragma unroll
                for (int w = 0; w < 4; ++w)
                    unpack2(acc[f2][p * 4 + w], lo[w], hi[w]);
                int fe = fbase + 2 * f2;
                float4 ve = make_float4(lo[0], lo[1], lo[2], lo[3]);
                float4 vo = make_float4(hi[0], hi[1], hi[2], hi[3]);
                *reinterpret_cast<float4*>(out + ((size_t)(n * FF + fe)     * OW + wg)) = ve;
                *reinterpret_cast<float4*>(out + ((size_t)(n * FF + fe + 1) * OW + wg)) = vo;
            }
        }
    }
}

extern "C" void kernel_launch(void* const* d_in, const int* in_sizes, int n_in,
                              void* d_out, int out_size) {
    const float* x    = (const float*)d_in[0];
    const float* filt = (const float*)d_in[1];
    const float* bias = (const float*)d_in[2];
    float* out = (float*)d_out;

    // 1) pre-pack filter pairs into device-global scratch (graph-capturable)
    const int total = CC * (FF / 2) * WW;
    pack_filt_kernel<<<(total + 255) / 256, 256>>>(filt);

    // 2) main correlation
    dim3 grid(WX / W_TILE, NN);   // (32, 64)
    corr1d_kernel<<<grid, THREADS>>>(x, bias, out);
}